// round 14
// baseline (speedup 1.0000x reference)
#include <cuda_runtime.h>
#include <cuda_fp16.h>
#include <cstdint>

typedef unsigned int u32;
typedef unsigned long long u64;

#define Hd   512
#define SPd  520
#define MTr  16384
#define PSZ  (32*SPd*Hd)
#define INTOFF 2048
#define CWL  (512*2560)
#define HWL  (1024*512)

// ---------------- static device scratch ----------------
__device__ __half g_P[2][3][PSZ];    // conv inputs per [dir][layer], padded
__device__ __half g_T[2][PSZ];       // conv output / hw1 input
__device__ __half g_U[2][PSZ];       // hw1 output / hw2 input
__device__ __half g_cW[2][3*CWL];    // conv weights [dir][layer][512 n][2560 k]
__device__ __half g_hW[2][6*HWL];    // hw weights   [dir][l*2+j][1024 q][512 k]

// scheduler: completion counters [layer][phase][z][mtile] + prep counters + ticket
__device__ int g_sync[3][3][2][128];
__device__ int g_pc[32];             // 0:act(256) 1..3:pads l(4) 4..9:cw[z][l](64) 10..21:hw[z][lw](32)
__device__ int g_tix;

// ---------------- helpers ----------------
__device__ __forceinline__ u32 s2u(const void* p) {
    u32 a; asm("{ .reg .u64 t; cvta.to.shared.u64 t, %1; cvt.u32.u64 %0, t; }"
               : "=r"(a) : "l"(p)); return a;
}
__device__ __forceinline__ void cp16(u32 d, const void* s) {
    asm volatile("cp.async.cg.shared.global [%0], [%1], 16;" :: "r"(d), "l"(s) : "memory");
}
__device__ __forceinline__ void ldsm4(u32* r, u32 a) {
    asm volatile("ldmatrix.sync.aligned.m8n8.x4.shared.b16 {%0,%1,%2,%3}, [%4];"
                 : "=r"(r[0]), "=r"(r[1]), "=r"(r[2]), "=r"(r[3]) : "r"(a));
}
__device__ __forceinline__ void mma16816(float* d, const u32* a, const u32* b) {
    asm volatile("mma.sync.aligned.m16n8k16.row.col.f32.f16.f16.f32 "
                 "{%0,%1,%2,%3}, {%4,%5,%6,%7}, {%8,%9}, {%0,%1,%2,%3};"
                 : "+f"(d[0]), "+f"(d[1]), "+f"(d[2]), "+f"(d[3])
                 : "r"(a[0]), "r"(a[1]), "r"(a[2]), "r"(a[3]), "r"(b[0]), "r"(b[1]));
}
__device__ __forceinline__ size_t crow(int r) {
    return (size_t)(r + ((r >> 9) << 3)) * Hd;   // conv-mapped padded row
}
__device__ __forceinline__ u32 swz(int row, int ch) {   // 64B-row XOR swizzle
    return (u32)(row * 64 + ((ch ^ ((row >> 1) & 3)) << 4));
}
__device__ __forceinline__ void dwait(int* c, int tgt) {
    while (atomicAdd(c, 0) < tgt) __nanosleep(64);
}

#define STAGE 16384            // per chunk: A 8KB + B 8KB
#define NSTG  6
#define DSM   (128 + NSTG*STAGE)   // 96.1KB; staging (67.7KB) unions in; occ2

#define NPREP 1036
#define NMAIN (3*5120)

struct Args {
    const float *bc_f, *bc_b;    // conv biases [3][512]
    const float *bh_f, *bh_b;    // hw biases   [6][1024]
    const float *inp, *padf, *padb;
    const float *cwf, *cwb, *hwf, *hwb;   // raw fp32 weights
    float* out;
};

// ============ fully-fused 3-layer kernel + in-queue prep tickets ============
// prep tickets [0,1036): pads(12), act(256), cw-l0(128), hw-lw0(64), hw-lw1(64),
//   cw-l1(128), hw-lw2(64), hw-lw3(64), cw-l2(128), hw-lw4(64), hw-lw5(64)
// main tickets [1036, 1036+15360): as R13 (layer-major conv/hw1/hw2)
__global__ __launch_bounds__(256, 2)
void fused_kernel(Args a)
{
    extern __shared__ char dsm[];
    const u32 base = (s2u(dsm) + 127) & ~127u;
    float* sstg = (float*)(dsm + (base - s2u(dsm)));   // UNION with pipeline stages

    __shared__ int s_t;
    const int tid = threadIdx.x;
    if (tid == 0) s_t = atomicAdd(&g_tix, 1);
    __syncthreads();
    const int t = s_t;

    // =========================== PREP TICKETS ===========================
    if (t < NPREP) {
        int pcidx = -1;
        if (t < 12) {                         // pads: l = t>>2, xc = t&3
            const int l = t >> 2, xc = t & 3;
            for (int blk = 0; blk < 32; blk++) {
                int idx = (xc * 32 + blk) * 256 + tid;
                int e = idx << 2;
                int b = e >> 12; int rem = e & 4095; int p = rem >> 9; int h = rem & 511;
                const float* s = (p < 4) ? (a.padf + (size_t)l * 2048 + p * 512 + h)
                                         : (a.padb + (size_t)l * 2048 + (p - 4) * 512 + h);
                int row = (p < 4) ? (b * 520 + p) : (b * 520 + 516 + (p - 4));
                float4 v = *(const float4*)s;
                __half2 h2[2];
                h2[0] = __float22half2_rn(make_float2(v.x, v.y));
                h2[1] = __float22half2_rn(make_float2(v.z, v.w));
                size_t o = (size_t)row * 512 + h;
                *(uint2*)(&g_P[0][l][0] + o) = *(uint2*)h2;
                *(uint2*)(&g_P[1][l][0] + o) = *(uint2*)h2;
            }
            pcidx = 1 + l;
        } else if (t < 268) {                 // act split: 256 tickets x 32 blocks
            const int at = t - 12;
            for (int blk = 0; blk < 32; blk++) {
                int idx = (at * 32 + blk) * 256 + tid;
                int e = idx << 2;
                int r = e >> 9, h = e & 511;
                float4 v = *(const float4*)(a.inp + e);
                __half2 h2[2];
                h2[0] = __float22half2_rn(make_float2(v.x, v.y));
                h2[1] = __float22half2_rn(make_float2(v.z, v.w));
                size_t o = crow(r) + h + INTOFF;
                *(uint2*)(&g_P[0][0][0] + o) = *(uint2*)h2;
                *(uint2*)(&g_P[1][0][0] + o) = *(uint2*)h2;
            }
            pcidx = 0;
        } else {
            // weight prep, laid out per layer group
            int q = t - 268;
            int kind, l, z, sub;
            // group sizes: cw(128) hw(64) hw(64) per layer
            const int gl = 256;               // per-layer group total
            l = q / gl; q -= l * gl;
            if (q < 128)      { kind = 0; z = q >> 6; sub = q & 63; }           // convW l
            else if (q < 192) { kind = 1; z = (q - 128) >> 5; sub = (q - 128) & 31; } // hw lw=2l
            else              { kind = 2; z = (q - 192) >> 5; sub = (q - 192) & 31; } // hw lw=2l+1
            if (kind == 0) {
                const float* W = (z ? a.cwb : a.cwf);
                __half* O = &g_cW[z][0];
                for (int it = 0; it < 10; it++) {
                    int unit = it * 256 + tid;            // 2560 units: 8 n x 320 k
                    int nl = unit / 320, ku = unit % 320;
                    int n = sub * 8 + nl, k0 = ku * 8;
                    const float* src = W + (size_t)l * 2560 * 512 + (size_t)k0 * 512 + n;
                    __half2 h2[4];
#pragma unroll
                    for (int tt = 0; tt < 4; tt++)
                        h2[tt] = __float22half2_rn(make_float2(src[(2*tt) * 512], src[(2*tt + 1) * 512]));
                    size_t o = ((size_t)l * 512 + n) * 2560 + k0;
                    *(uint4*)(O + o) = *(uint4*)h2;
                }
                pcidx = 4 + z * 3 + l;
            } else {
                const int lw = 2 * l + (kind - 1);
                const float* W = (z ? a.hwb : a.hwf);
                __half* O = &g_hW[z][0];
                for (int it = 0; it < 8; it++) {
                    int unit = it * 256 + tid;            // 2048 units: 32 np x 64 k
                    int nl = unit / 64, ku = unit % 64;
                    int np = sub * 32 + nl, k0 = ku * 8;
                    int f = (np < 512) ? np : (np - 512);
                    int qq = (f >> 6) * 128 + ((np < 512) ? (f & 63) : (64 + (f & 63)));
                    const float* src = W + (size_t)lw * 512 * 1024 + (size_t)k0 * 1024 + np;
                    __half2 h2[4];
#pragma unroll
                    for (int tt = 0; tt < 4; tt++)
                        h2[tt] = __float22half2_rn(make_float2(src[(2*tt) * 1024], src[(2*tt + 1) * 1024]));
                    size_t o = ((size_t)lw * 1024 + qq) * 512 + k0;
                    *(uint4*)(O + o) = *(uint4*)h2;
                }
                pcidx = 10 + z * 6 + lw;
            }
        }
        __threadfence();
        __syncthreads();
        if (tid == 0) atomicAdd(&g_pc[pcidx], 1);
        return;
    }

    // =========================== MAIN TICKETS ===========================
    const int tm = t - NPREP;
    const int layer = tm / 5120;
    const int u = tm - layer * 5120;
    int phase, m, n, z;
    if (u < 1024)      { phase = 0; z = u & 1; n = (u >> 1) & 3; m = u >> 3; }
    else if (u < 3072) { int v = u - 1024; phase = 1; z = v & 1; n = (v >> 1) & 7; m = v >> 4; }
    else               { int v = u - 3072; phase = 2; z = v & 1; n = (v >> 1) & 7; m = v >> 4; }

    int K;
    const __half *A, *W, *X = nullptr;
    const float* bias;
    __half* Y = nullptr; float* op = nullptr;
    if (phase == 0) {
        K = 2560;
        A = &g_P[z][layer][0] + (z ? 2048 : 0);      // fwd window off 0, bwd off W rows
        W = &g_cW[z][(size_t)layer * CWL];
        bias = (z ? a.bc_b : a.bc_f) + layer * 512;
        Y = &g_T[z][INTOFF];
    } else if (phase == 1) {
        K = 512;
        A = X = &g_T[z][INTOFF];
        W = &g_hW[z][(size_t)(layer * 2) * HWL];
        bias = (z ? a.bh_b : a.bh_f) + (size_t)(layer * 2) * 1024;
        Y = &g_U[z][INTOFF];
    } else {
        K = 512;
        A = X = &g_U[z][INTOFF];
        W = &g_hW[z][(size_t)(layer * 2 + 1) * HWL];
        bias = (z ? a.bh_b : a.bh_f) + (size_t)(layer * 2 + 1) * 1024;
        Y = (layer < 2) ? &g_P[z][layer + 1][INTOFF] : nullptr;
        op = a.out + (size_t)layer * MTr * 1024 + z * 512;
    }

    // ---- dependency wait (tid0 spins, broadcast via syncthreads) ----
    if (tid == 0) {
        if (phase == 0) {
            dwait(&g_pc[4 + z * 3 + layer], 64);     // conv weights ready
            dwait(&g_pc[1 + layer], 4);              // pads ready
            if (layer == 0) {
                dwait(&g_pc[0], 256);                // act ready
            } else {
                dwait(&g_sync[layer - 1][2][z][m], 8);
                if (z == 0) { if ((m & 3) != 0) dwait(&g_sync[layer - 1][2][0][m - 1], 8); }
                else        { if ((m & 3) != 3) dwait(&g_sync[layer - 1][2][1][m + 1], 8); }
            }
        } else if (phase == 1) {
            dwait(&g_pc[10 + z * 6 + 2 * layer], 32);
            dwait(&g_sync[layer][0][z][m], 4);
        } else {
            dwait(&g_pc[10 + z * 6 + 2 * layer + 1], 32);
            dwait(&g_sync[layer][1][z][m], 8);
        }
        __threadfence();
    }
    __syncthreads();

    const int NP   = K >> 6;                 // chunk-pairs (K/64)
    const int lane = tid & 31;
    const int wid  = tid >> 5;
    const int wm   = (wid >> 2) * 64;
    const int wn   = (wid & 3) * 32;
    const int m0   = m << 7;
    const int nb0  = n << 7;

    const __half* aSrc[2]; u32 aOff[2];
    const __half* bSrc[2]; u32 bOff[2];
#pragma unroll
    for (int it = 0; it < 2; it++) {
        int v = tid + it * 256;
        int row = v >> 2, ch = v & 3;
        aSrc[it] = A + crow(m0 + row) + ch * 8;
        aOff[it] = swz(row, ch);
        bSrc[it] = W + (size_t)(nb0 + row) * K + ch * 8;
        bOff[it] = 8192u + swz(row, ch);
    }

    auto load_chunk = [&](int c, int st) {
        const u32 sb = base + (u32)(st * STAGE);
        const int kc = c * 32;
#pragma unroll
        for (int it = 0; it < 2; it++) cp16(sb + aOff[it], aSrc[it] + kc);
#pragma unroll
        for (int it = 0; it < 2; it++) cp16(sb + bOff[it], bSrc[it] + kc);
    };
    auto load_pair = [&](int p, int st) {
        load_chunk(2 * p, st);
        load_chunk(2 * p + 1, st + 1);
        asm volatile("cp.async.commit_group;" ::: "memory");
    };

    float acc[4][4][4];
#pragma unroll
    for (int i = 0; i < 4; i++)
#pragma unroll
        for (int j = 0; j < 4; j++)
#pragma unroll
            for (int q = 0; q < 4; q++) acc[i][j][q] = 0.f;

    load_pair(0, 0);
    load_pair(1, 2);

    const int ar = lane & 15;
    const int ac = lane >> 4;
    const int br = (lane & 7) + ((lane & 16) >> 1);
    const int bc = (lane >> 3) & 1;

    int cst = 0, lst = 4;                    // compute stage, load stage (even, mod 6)
    for (int p = 0; p < NP; p++) {
        asm volatile("cp.async.wait_group 1;" ::: "memory");
        __syncthreads();
        if (p + 2 < NP) load_pair(p + 2, lst);
        else            asm volatile("cp.async.commit_group;" ::: "memory");

#pragma unroll
        for (int h = 0; h < 2; h++) {
            const u32 sb = base + (u32)((cst + h) * STAGE);
#pragma unroll
            for (int s = 0; s < 2; s++) {
                u32 bfb[8], afr[4][4];
                ldsm4(&bfb[0], sb + 8192 + swz(wn + br, 2 * s + bc));
                ldsm4(&bfb[4], sb + 8192 + swz(wn + 16 + br, 2 * s + bc));
#pragma unroll
                for (int i = 0; i < 4; i++)
                    ldsm4(afr[i], sb + swz(wm + i * 16 + ar, 2 * s + ac));
#pragma unroll
                for (int i = 0; i < 4; i++)
#pragma unroll
                    for (int j = 0; j < 4; j++)
                        mma16816(acc[i][j], afr[i], &bfb[j * 2]);
            }
        }
        cst = (cst == 4) ? 0 : cst + 2;
        lst = (lst == 4) ? 0 : lst + 2;
    }

    // ---- stage accumulators to smem (pipeline smem now dead) ----
    __syncthreads();
#pragma unroll
    for (int i = 0; i < 4; i++)
#pragma unroll
        for (int j = 0; j < 4; j++) {
            int r0 = wm + i * 16 + (lane >> 2);
            int cc = wn + j * 8 + (lane & 3) * 2;
            *(float2*)&sstg[r0 * 132 + cc]       = make_float2(acc[i][j][0], acc[i][j][1]);
            *(float2*)&sstg[(r0 + 8) * 132 + cc] = make_float2(acc[i][j][2], acc[i][j][3]);
        }
    __syncthreads();

    // ---- fused, coalesced epilogue ----
    const int r  = tid >> 1;
    const int gr = m0 + r;

    if (phase == 0) {
        const int c0 = (tid & 1) * 64;
#pragma unroll
        for (int c8 = 0; c8 < 8; c8++) {
            const int cb = c0 + c8 * 8;
            __half2 hv[4];
#pragma unroll
            for (int tt = 0; tt < 4; tt++) {
                float v0 = fmaxf(sstg[r * 132 + cb + 2*tt]     + bias[nb0 + cb + 2*tt],     0.f);
                float v1 = fmaxf(sstg[r * 132 + cb + 2*tt + 1] + bias[nb0 + cb + 2*tt + 1], 0.f);
                hv[tt] = __float22half2_rn(make_float2(v0, v1));
            }
            *(uint4*)(Y + crow(gr) + nb0 + cb) = *(uint4*)hv;
        }
    } else {
        const int fbase = n * 64;
        const int fl0   = (tid & 1) * 32;
#pragma unroll
        for (int c8 = 0; c8 < 4; c8++) {
            const int fl = fl0 + c8 * 8;
            const int f  = fbase + fl;
            uint4 x4 = *(const uint4*)(X + crow(gr) + f);
            __half2 hv[4];
            float ov[8];
#pragma unroll
            for (int tt = 0; tt < 4; tt++) {
                float2 x2 = __half22float2(*(__half2*)&((u32*)&x4)[tt]);
                float nl0 = sstg[r * 132 + fl + 2*tt]       + bias[f + 2*tt];
                float nl1 = sstg[r * 132 + fl + 2*tt + 1]   + bias[f + 2*tt + 1];
                float gt0 = sstg[r * 132 + 64 + fl + 2*tt]     + bias[512 + f + 2*tt];
                float gt1 = sstg[r * 132 + 64 + fl + 2*tt + 1] + bias[512 + f + 2*tt + 1];
                float s0 = 1.f / (1.f + __expf(-gt0));
                float s1 = 1.f / (1.f + __expf(-gt1));
                float o0 = s0 * x2.x + (1.f - s0) * fmaxf(nl0, 0.f);
                float o1 = s1 * x2.y + (1.f - s1) * fmaxf(nl1, 0.f);
                hv[tt] = __float22half2_rn(make_float2(o0, o1));
                ov[2*tt] = o0; ov[2*tt + 1] = o1;
            }
            if (Y) *(uint4*)(Y + crow(gr) + f) = *(uint4*)hv;
            if (op) {
                *(float4*)(op + (size_t)gr * 1024 + f)     = *(float4*)&ov[0];
                *(float4*)(op + (size_t)gr * 1024 + f + 4) = *(float4*)&ov[4];
            }
        }
    }

    // ---- publish completion ----
    __threadfence();
    __syncthreads();
    if (tid == 0) atomicAdd(&g_sync[layer][phase][z][m], 1);
}

// ================= zero kernel (must precede fused each call) =================
__global__ void zero_sync() {
    int i = blockIdx.x * 256 + threadIdx.x;
    if (i < 3 * 3 * 2 * 128) ((int*)g_sync)[i] = 0;
    if (i < 32) g_pc[i] = 0;
    if (i == 0) g_tix = 0;
}

// ================= host =================
extern "C" void kernel_launch(void* const* d_in, const int* in_sizes, int n_in,
                              void* d_out, int out_size)
{
    const float* inputs   = (const float*)d_in[0];
    const float* fwd_pads = (const float*)d_in[2];
    const float* bwd_pads = (const float*)d_in[3];
    const float* fwd_W    = (const float*)d_in[4];
    const float* fwd_bi   = (const float*)d_in[5];
    const float* bwd_W    = (const float*)d_in[6];
    const float* bwd_bi   = (const float*)d_in[7];
    const float* fwd_hw_W = (const float*)d_in[8];
    const float* fwd_hw_b = (const float*)d_in[9];
    const float* bwd_hw_W = (const float*)d_in[10];
    const float* bwd_hw_b = (const float*)d_in[11];
    float* out = (float*)d_out;

    cudaFuncSetAttribute(fused_kernel, cudaFuncAttributeMaxDynamicSharedMemorySize, DSM);

    zero_sync<<<9, 256>>>();

    Args a{};
    a.bc_f = fwd_bi;   a.bc_b = bwd_bi;
    a.bh_f = fwd_hw_b; a.bh_b = bwd_hw_b;
    a.inp = inputs; a.padf = fwd_pads; a.padb = bwd_pads;
    a.cwf = fwd_W; a.cwb = bwd_W; a.hwf = fwd_hw_W; a.hwb = bwd_hw_W;
    a.out = out;
    fused_kernel<<<NPREP + NMAIN, 256, DSM>>>(a);
}

// round 16
// speedup vs baseline: 1.0154x; 1.0154x over previous
#include <cuda_runtime.h>
#include <cuda_fp16.h>
#include <cstdint>

typedef unsigned int u32;
typedef unsigned long long u64;

#define Hd   512
#define SPd  520
#define MTr  16384
#define PSZ  (32*SPd*Hd)
#define INTOFF 2048
#define CWL  (512*2560)
#define HWL  (1024*512)

// ---------------- static device scratch ----------------
__device__ __half g_P[2][3][PSZ];    // conv inputs per [dir][layer], padded
__device__ __half g_T[2][PSZ];       // conv output / hw1 input
__device__ __half g_U[2][PSZ];       // hw1 output / hw2 input
__device__ __half g_cW[2][3*CWL];    // conv weights [dir][layer][512 n][2560 k]
__device__ __half g_hW[2][6*HWL];    // hw weights   [dir][l*2+j][1024 q][512 k]

// scheduler: completion counters [layer][phase][z][mtile] + weight-prep counters + ticket
__device__ int g_sync[3][3][2][128];
__device__ int g_pc[16];   // 0..3: cw[(l-1)*2+z] tgt 64; 4..11: hw[(lw-2)*2+z] tgt 32
__device__ int g_tix;

// ---------------- helpers ----------------
__device__ __forceinline__ u32 s2u(const void* p) {
    u32 a; asm("{ .reg .u64 t; cvta.to.shared.u64 t, %1; cvt.u32.u64 %0, t; }"
               : "=r"(a) : "l"(p)); return a;
}
__device__ __forceinline__ void cp16(u32 d, const void* s) {
    asm volatile("cp.async.cg.shared.global [%0], [%1], 16;" :: "r"(d), "l"(s) : "memory");
}
__device__ __forceinline__ void ldsm4(u32* r, u32 a) {
    asm volatile("ldmatrix.sync.aligned.m8n8.x4.shared.b16 {%0,%1,%2,%3}, [%4];"
                 : "=r"(r[0]), "=r"(r[1]), "=r"(r[2]), "=r"(r[3]) : "r"(a));
}
__device__ __forceinline__ void mma16816(float* d, const u32* a, const u32* b) {
    asm volatile("mma.sync.aligned.m16n8k16.row.col.f32.f16.f16.f32 "
                 "{%0,%1,%2,%3}, {%4,%5,%6,%7}, {%8,%9}, {%0,%1,%2,%3};"
                 : "+f"(d[0]), "+f"(d[1]), "+f"(d[2]), "+f"(d[3])
                 : "r"(a[0]), "r"(a[1]), "r"(a[2]), "r"(a[3]), "r"(b[0]), "r"(b[1]));
}
__device__ __forceinline__ size_t crow(int r) {
    return (size_t)(r + ((r >> 9) << 3)) * Hd;   // conv-mapped padded row
}
__device__ __forceinline__ u32 swz(int row, int ch) {   // 64B-row XOR swizzle
    return (u32)(row * 64 + ((ch ^ ((row >> 1) & 3)) << 4));
}
__device__ __forceinline__ void dwait(int* c, int tgt) {
    while (atomicAdd(c, 0) < tgt) __nanosleep(64);
}

#define STAGE 16384            // per chunk: A 8KB + B 8KB
#define NSTG  6
#define DSM   (128 + NSTG*STAGE)   // 96.1KB; staging (67.7KB) unions in; occ2

#define NPREP 512              // layers 1-2 weight-conversion tickets
#define NTOT  (15360 + NPREP)

struct Args {
    const float *bc_f, *bc_b;    // conv biases [3][512]
    const float *bh_f, *bh_b;    // hw biases   [6][1024]
    const float *cwf, *cwb, *hwf, *hwb;   // raw fp32 weights (for l1/l2 tickets)
    float* out;
};

// ============ fully-fused 3-layer kernel via global ticket queue ============
// ticket t:
//   [0,1024):      conv l0       (u = t)
//   [1024,1536):   PREP l1/l2 weights (q = t-1024)
//   [1536,NTOT):   remaining main tickets, idx = t-512 in R13 numbering
// main decode (idx in [0,15360)): layer = idx/5120, u = idx%5120
//   u in [0,1024):    conv  z=u&1, n=(u>>1)&3, m=u>>3
//   u in [1024,3072): hw1   (v=u-1024) z=v&1, n=(v>>1)&7, m=v>>4
//   u in [3072,5120): hw2   (v=u-3072)
// deps: as R13, plus l>=1 tiles gate on g_pc weight counters (older tickets).
__global__ __launch_bounds__(256, 2)
void fused_kernel(Args a)
{
    extern __shared__ char dsm[];
    const u32 base = (s2u(dsm) + 127) & ~127u;
    float* sstg = (float*)(dsm + (base - s2u(dsm)));   // UNION with pipeline stages

    __shared__ int s_t;
    const int tid = threadIdx.x;
    if (tid == 0) s_t = atomicAdd(&g_tix, 1);
    __syncthreads();
    const int t = s_t;

    // =================== PREP TICKETS (l1/l2 weights) ===================
    if (t >= 1024 && t < 1024 + NPREP) {
        int q = t - 1024;
        const int l = 1 + (q >> 8);           // 1 or 2
        q &= 255;
        int pcidx;
        if (q < 128) {                        // conv weights: z = q>>6, sub = q&63
            const int z = q >> 6, sub = q & 63;
            const float* W = (z ? a.cwb : a.cwf);
            __half* O = &g_cW[z][0];
            for (int it = 0; it < 10; it++) {
                int unit = it * 256 + tid;            // 2560 units: 8 n x 320 k
                int nl = unit / 320, ku = unit % 320;
                int n = sub * 8 + nl, k0 = ku * 8;
                const float* src = W + (size_t)l * 2560 * 512 + (size_t)k0 * 512 + n;
                __half2 h2[4];
#pragma unroll
                for (int tt = 0; tt < 4; tt++)
                    h2[tt] = __float22half2_rn(make_float2(src[(2*tt) * 512], src[(2*tt + 1) * 512]));
                size_t o = ((size_t)l * 512 + n) * 2560 + k0;
                *(uint4*)(O + o) = *(uint4*)h2;
            }
            pcidx = (l - 1) * 2 + z;
        } else {                              // hw weights: kind=1/2, z, sub
            const int kind = (q < 192) ? 1 : 2;
            const int qq0 = q - (kind == 1 ? 128 : 192);
            const int z = qq0 >> 5, sub = qq0 & 31;
            const int lw = 2 * l + (kind - 1);
            const float* W = (z ? a.hwb : a.hwf);
            __half* O = &g_hW[z][0];
            for (int it = 0; it < 8; it++) {
                int unit = it * 256 + tid;            // 2048 units: 32 np x 64 k
                int nl = unit / 64, ku = unit % 64;
                int np = sub * 32 + nl, k0 = ku * 8;
                int f = (np < 512) ? np : (np - 512);
                int qq = (f >> 6) * 128 + ((np < 512) ? (f & 63) : (64 + (f & 63)));
                const float* src = W + (size_t)lw * 512 * 1024 + (size_t)k0 * 1024 + np;
                __half2 h2[4];
#pragma unroll
                for (int tt = 0; tt < 4; tt++)
                    h2[tt] = __float22half2_rn(make_float2(src[(2*tt) * 1024], src[(2*tt + 1) * 1024]));
                size_t o = ((size_t)lw * 1024 + qq) * 512 + k0;
                *(uint4*)(O + o) = *(uint4*)h2;
            }
            pcidx = 4 + (lw - 2) * 2 + z;
        }
        __threadfence();
        __syncthreads();
        if (tid == 0) atomicAdd(&g_pc[pcidx], 1);
        return;
    }

    // =========================== MAIN TICKETS ===========================
    const int idx = (t < 1024) ? t : (t - NPREP);
    const int layer = idx / 5120;
    const int u = idx - layer * 5120;
    int phase, m, n, z;
    if (u < 1024)      { phase = 0; z = u & 1; n = (u >> 1) & 3; m = u >> 3; }
    else if (u < 3072) { int v = u - 1024; phase = 1; z = v & 1; n = (v >> 1) & 7; m = v >> 4; }
    else               { int v = u - 3072; phase = 2; z = v & 1; n = (v >> 1) & 7; m = v >> 4; }

    int K;
    const __half *A, *W, *X = nullptr;
    const float* bias;
    __half* Y = nullptr; float* op = nullptr;
    if (phase == 0) {
        K = 2560;
        A = &g_P[z][layer][0] + (z ? 2048 : 0);      // fwd window off 0, bwd off W rows
        W = &g_cW[z][(size_t)layer * CWL];
        bias = (z ? a.bc_b : a.bc_f) + layer * 512;
        Y = &g_T[z][INTOFF];
    } else if (phase == 1) {
        K = 512;
        A = X = &g_T[z][INTOFF];
        W = &g_hW[z][(size_t)(layer * 2) * HWL];
        bias = (z ? a.bh_b : a.bh_f) + (size_t)(layer * 2) * 1024;
        Y = &g_U[z][INTOFF];
    } else {
        K = 512;
        A = X = &g_U[z][INTOFF];
        W = &g_hW[z][(size_t)(layer * 2 + 1) * HWL];
        bias = (z ? a.bh_b : a.bh_f) + (size_t)(layer * 2 + 1) * 1024;
        Y = (layer < 2) ? &g_P[z][layer + 1][INTOFF] : nullptr;
        op = a.out + (size_t)layer * MTr * 1024 + z * 512;
    }

    // ---- dependency wait (tid0 spins, broadcast via syncthreads) ----
    if (tid == 0) {
        if (phase == 0) {
            if (layer > 0) {
                dwait(&g_pc[(layer - 1) * 2 + z], 64);   // conv weights l>=1
                dwait(&g_sync[layer - 1][2][z][m], 8);
                if (z == 0) { if ((m & 3) != 0) dwait(&g_sync[layer - 1][2][0][m - 1], 8); }
                else        { if ((m & 3) != 3) dwait(&g_sync[layer - 1][2][1][m + 1], 8); }
            }
        } else if (phase == 1) {
            if (layer > 0) dwait(&g_pc[4 + (2 * layer - 2) * 2 + z], 32);
            dwait(&g_sync[layer][0][z][m], 4);
        } else {
            if (layer > 0) dwait(&g_pc[4 + (2 * layer - 1) * 2 + z], 32);
            dwait(&g_sync[layer][1][z][m], 8);
        }
        __threadfence();
    }
    __syncthreads();

    const int NP   = K >> 6;                 // chunk-pairs (K/64)
    const int lane = tid & 31;
    const int wid  = tid >> 5;
    const int wm   = (wid >> 2) * 64;
    const int wn   = (wid & 3) * 32;
    const int m0   = m << 7;
    const int nb0  = n << 7;

    const __half* aSrc[2]; u32 aOff[2];
    const __half* bSrc[2]; u32 bOff[2];
#pragma unroll
    for (int it = 0; it < 2; it++) {
        int v = tid + it * 256;
        int row = v >> 2, ch = v & 3;
        aSrc[it] = A + crow(m0 + row) + ch * 8;
        aOff[it] = swz(row, ch);
        bSrc[it] = W + (size_t)(nb0 + row) * K + ch * 8;
        bOff[it] = 8192u + swz(row, ch);
    }

    auto load_chunk = [&](int c, int st) {
        const u32 sb = base + (u32)(st * STAGE);
        const int kc = c * 32;
#pragma unroll
        for (int it = 0; it < 2; it++) cp16(sb + aOff[it], aSrc[it] + kc);
#pragma unroll
        for (int it = 0; it < 2; it++) cp16(sb + bOff[it], bSrc[it] + kc);
    };
    auto load_pair = [&](int p, int st) {
        load_chunk(2 * p, st);
        load_chunk(2 * p + 1, st + 1);
        asm volatile("cp.async.commit_group;" ::: "memory");
    };

    float acc[4][4][4];
#pragma unroll
    for (int i = 0; i < 4; i++)
#pragma unroll
        for (int j = 0; j < 4; j++)
#pragma unroll
            for (int q = 0; q < 4; q++) acc[i][j][q] = 0.f;

    load_pair(0, 0);
    load_pair(1, 2);

    const int ar = lane & 15;
    const int ac = lane >> 4;
    const int br = (lane & 7) + ((lane & 16) >> 1);
    const int bc = (lane >> 3) & 1;

    int cst = 0, lst = 4;                    // compute stage, load stage (even, mod 6)
    for (int p = 0; p < NP; p++) {
        asm volatile("cp.async.wait_group 1;" ::: "memory");
        __syncthreads();
        if (p + 2 < NP) load_pair(p + 2, lst);
        else            asm volatile("cp.async.commit_group;" ::: "memory");

#pragma unroll
        for (int h = 0; h < 2; h++) {
            const u32 sb = base + (u32)((cst + h) * STAGE);
#pragma unroll
            for (int s = 0; s < 2; s++) {
                u32 bfb[8], afr[4][4];
                ldsm4(&bfb[0], sb + 8192 + swz(wn + br, 2 * s + bc));
                ldsm4(&bfb[4], sb + 8192 + swz(wn + 16 + br, 2 * s + bc));
#pragma unroll
                for (int i = 0; i < 4; i++)
                    ldsm4(afr[i], sb + swz(wm + i * 16 + ar, 2 * s + ac));
#pragma unroll
                for (int i = 0; i < 4; i++)
#pragma unroll
                    for (int j = 0; j < 4; j++)
                        mma16816(acc[i][j], afr[i], &bfb[j * 2]);
            }
        }
        cst = (cst == 4) ? 0 : cst + 2;
        lst = (lst == 4) ? 0 : lst + 2;
    }

    // ---- stage accumulators to smem (pipeline smem now dead) ----
    __syncthreads();
#pragma unroll
    for (int i = 0; i < 4; i++)
#pragma unroll
        for (int j = 0; j < 4; j++) {
            int r0 = wm + i * 16 + (lane >> 2);
            int cc = wn + j * 8 + (lane & 3) * 2;
            *(float2*)&sstg[r0 * 132 + cc]       = make_float2(acc[i][j][0], acc[i][j][1]);
            *(float2*)&sstg[(r0 + 8) * 132 + cc] = make_float2(acc[i][j][2], acc[i][j][3]);
        }
    __syncthreads();

    // ---- fused, coalesced epilogue ----
    const int r  = tid >> 1;
    const int gr = m0 + r;

    if (phase == 0) {
        const int c0 = (tid & 1) * 64;
#pragma unroll
        for (int c8 = 0; c8 < 8; c8++) {
            const int cb = c0 + c8 * 8;
            __half2 hv[4];
#pragma unroll
            for (int tt = 0; tt < 4; tt++) {
                float v0 = fmaxf(sstg[r * 132 + cb + 2*tt]     + bias[nb0 + cb + 2*tt],     0.f);
                float v1 = fmaxf(sstg[r * 132 + cb + 2*tt + 1] + bias[nb0 + cb + 2*tt + 1], 0.f);
                hv[tt] = __float22half2_rn(make_float2(v0, v1));
            }
            *(uint4*)(Y + crow(gr) + nb0 + cb) = *(uint4*)hv;
        }
    } else {
        const int fbase = n * 64;
        const int fl0   = (tid & 1) * 32;
#pragma unroll
        for (int c8 = 0; c8 < 4; c8++) {
            const int fl = fl0 + c8 * 8;
            const int f  = fbase + fl;
            uint4 x4 = *(const uint4*)(X + crow(gr) + f);
            __half2 hv[4];
            float ov[8];
#pragma unroll
            for (int tt = 0; tt < 4; tt++) {
                float2 x2 = __half22float2(*(__half2*)&((u32*)&x4)[tt]);
                float nl0 = sstg[r * 132 + fl + 2*tt]       + bias[f + 2*tt];
                float nl1 = sstg[r * 132 + fl + 2*tt + 1]   + bias[f + 2*tt + 1];
                float gt0 = sstg[r * 132 + 64 + fl + 2*tt]     + bias[512 + f + 2*tt];
                float gt1 = sstg[r * 132 + 64 + fl + 2*tt + 1] + bias[512 + f + 2*tt + 1];
                float s0 = 1.f / (1.f + __expf(-gt0));
                float s1 = 1.f / (1.f + __expf(-gt1));
                float o0 = s0 * x2.x + (1.f - s0) * fmaxf(nl0, 0.f);
                float o1 = s1 * x2.y + (1.f - s1) * fmaxf(nl1, 0.f);
                hv[tt] = __float22half2_rn(make_float2(o0, o1));
                ov[2*tt] = o0; ov[2*tt + 1] = o1;
            }
            if (Y) *(uint4*)(Y + crow(gr) + f) = *(uint4*)hv;
            if (op) {
                *(float4*)(op + (size_t)gr * 1024 + f)     = *(float4*)&ov[0];
                *(float4*)(op + (size_t)gr * 1024 + f + 4) = *(float4*)&ov[4];
            }
        }
    }

    // ---- publish completion ----
    __threadfence();
    __syncthreads();
    if (tid == 0) atomicAdd(&g_sync[layer][phase][z][m], 1);
}

// ================= prep kernels (layer-0 critical path only) =================
__global__ void prep_convW0(const float* __restrict__ Wf, const float* __restrict__ Wb) {
    // layer 0 only: grid (640, 2)
    int gid = blockIdx.x * blockDim.x + threadIdx.x;
    const float* W = blockIdx.y ? Wb : Wf;
    __half* O = &g_cW[blockIdx.y][0];
    int w = gid >> 5;
    int lane = threadIdx.x & 31;
    int n = (w / 320) * 32 + lane; int k0 = (w % 320) * 8;
    const float* src = W + (size_t)k0 * 512 + n;
    __half2 h2[4];
#pragma unroll
    for (int t = 0; t < 4; t++)
        h2[t] = __float22half2_rn(make_float2(src[(2*t) * 512], src[(2*t + 1) * 512]));
    size_t o = (size_t)n * 2560 + k0;
    *(uint4*)(O + o) = *(uint4*)h2;
}

__global__ void prep_hwW01(const float* __restrict__ Wf, const float* __restrict__ Wb) {
    // lw 0 and 1 only: grid (512, 2)
    int gid = blockIdx.x * blockDim.x + threadIdx.x;
    const float* W = blockIdx.y ? Wb : Wf;
    __half* O = &g_hW[blockIdx.y][0];
    int w = gid >> 5;
    int lane = threadIdx.x & 31;
    int lw = w / (32 * 64); int rem = w % (32 * 64);
    int np = (rem / 64) * 32 + lane; int k0 = (rem % 64) * 8;
    int f = (np < 512) ? np : (np - 512);
    int q = (f >> 6) * 128 + ((np < 512) ? (f & 63) : (64 + (f & 63)));
    const float* src = W + (size_t)lw * 512 * 1024 + (size_t)k0 * 1024 + np;
    __half2 h2[4];
#pragma unroll
    for (int t = 0; t < 4; t++)
        h2[t] = __float22half2_rn(make_float2(src[(2*t) * 1024], src[(2*t + 1) * 1024]));
    size_t o = ((size_t)lw * 1024 + q) * 512 + k0;
    *(uint4*)(O + o) = *(uint4*)h2;
}

__global__ void prep_act(const float* __restrict__ in) {
    int idx = blockIdx.x * 256 + threadIdx.x;
    // fold scheduler zeroing in
    if (idx < 3 * 3 * 2 * 128) ((int*)g_sync)[idx] = 0;
    if (idx < 16) g_pc[idx] = 0;
    if (idx == 0) g_tix = 0;
    int e = idx << 2;
    int r = e >> 9, h = e & 511;
    float4 v = *(const float4*)(in + e);
    __half2 h2[2];
    h2[0] = __float22half2_rn(make_float2(v.x, v.y));
    h2[1] = __float22half2_rn(make_float2(v.z, v.w));
    size_t o = crow(r) + h + INTOFF;
    *(uint2*)(&g_P[0][0][0] + o) = *(uint2*)h2;
    *(uint2*)(&g_P[1][0][0] + o) = *(uint2*)h2;
}

__global__ void prep_pads(const float* __restrict__ fp, const float* __restrict__ bp) {
    // blockIdx.y = layer; fill pad rows of g_P[0][l] and g_P[1][l]
    int l = blockIdx.y;
    int idx = blockIdx.x * 256 + threadIdx.x;
    int e = idx << 2;
    int b = e >> 12; int rem = e & 4095; int p = rem >> 9; int h = rem & 511;
    const float* s = (p < 4) ? (fp + (size_t)l * 2048 + p * 512 + h)
                             : (bp + (size_t)l * 2048 + (p - 4) * 512 + h);
    int row = (p < 4) ? (b * 520 + p) : (b * 520 + 516 + (p - 4));
    float4 v = *(const float4*)s;
    __half2 h2[2];
    h2[0] = __float22half2_rn(make_float2(v.x, v.y));
    h2[1] = __float22half2_rn(make_float2(v.z, v.w));
    size_t o = (size_t)row * 512 + h;
    *(uint2*)(&g_P[0][l][0] + o) = *(uint2*)h2;
    *(uint2*)(&g_P[1][l][0] + o) = *(uint2*)h2;
}

// ================= host =================
extern "C" void kernel_launch(void* const* d_in, const int* in_sizes, int n_in,
                              void* d_out, int out_size)
{
    const float* inputs   = (const float*)d_in[0];
    const float* fwd_pads = (const float*)d_in[2];
    const float* bwd_pads = (const float*)d_in[3];
    const float* fwd_W    = (const float*)d_in[4];
    const float* fwd_bi   = (const float*)d_in[5];
    const float* bwd_W    = (const float*)d_in[6];
    const float* bwd_bi   = (const float*)d_in[7];
    const float* fwd_hw_W = (const float*)d_in[8];
    const float* fwd_hw_b = (const float*)d_in[9];
    const float* bwd_hw_W = (const float*)d_in[10];
    const float* bwd_hw_b = (const float*)d_in[11];
    float* out = (float*)d_out;

    cudaFuncSetAttribute(fused_kernel, cudaFuncAttributeMaxDynamicSharedMemorySize, DSM);

    prep_act<<<8192, 256>>>(inputs);
    prep_convW0<<<dim3(640,2), 256>>>(fwd_W, bwd_W);
    prep_hwW01<<<dim3(512,2), 256>>>(fwd_hw_W, bwd_hw_W);
    prep_pads<<<dim3(128,3), 256>>>(fwd_pads, bwd_pads);

    Args a{};
    a.bc_f = fwd_bi;   a.bc_b = bwd_bi;
    a.bh_f = fwd_hw_b; a.bh_b = bwd_hw_b;
    a.cwf = fwd_W; a.cwb = bwd_W; a.hwf = fwd_hw_W; a.hwb = bwd_hw_W;
    a.out = out;
    fused_kernel<<<NTOT, 256, DSM>>>(a);
}